// round 12
// baseline (speedup 1.0000x reference)
#include <cuda_runtime.h>
#include <math_constants.h>

// EnhancedLIFNeuron: B=128, T=128, F=2048, KW=5
// inputs: x[B*T*F] f32, init_threshold[1], conv_w[5], conv_b[1], spatial_attn[1]
// output: spikes[B,T,F] then mem[B,F], f32.
//
// Register-resident design: each thread owns one (b,f) lane and keeps the whole
// T-column (128 floats) in registers. x is read from DRAM exactly once.

#define TT     128
#define FF     2048
#define BB     128
#define BLOCK  128

__global__ __launch_bounds__(BLOCK, 2)
void lif_fused_kernel(const float* __restrict__ x,
                      const float* __restrict__ thr_p,
                      const float* __restrict__ cw,
                      const float* __restrict__ cb,
                      const float* __restrict__ sa,
                      float* __restrict__ out)
{
    const int g = blockIdx.x * BLOCK + threadIdx.x;   // lane id in [0, B*F)
    const int f = g & (FF - 1);
    const int b = g >> 11;                            // FF = 2^11

    const float* __restrict__ xp = x + (size_t)b * TT * FF + f;
    float* __restrict__ op       = out + (size_t)b * TT * FF + f;

    const float w0 = cw[0], w1 = cw[1], w2 = cw[2], w3 = cw[3], w4 = cw[4];
    const float bias = cb[0];
    const float thr0 = thr_p[0];
    const float satt = sa[0];

    // ---------- load entire column into registers (single DRAM read of x) ----------
    float xv[TT];
    #pragma unroll
    for (int t = 0; t < TT; ++t)
        xv[t] = __ldcs(&xp[t * FF]);    // streaming: no reuse ever

    // ---------- sum over t from registers ----------
    float s0 = 0.f, s1 = 0.f, s2 = 0.f, s3 = 0.f;
    #pragma unroll
    for (int t = 0; t < TT; t += 4) {
        s0 += xv[t + 0];
        s1 += xv[t + 1];
        s2 += xv[t + 2];
        s3 += xv[t + 3];
    }
    const float S = (s0 + s1) + (s2 + s3);

    // analytic sum of conv over t (linear conv, SAME zero padding)
    const float wsum = w0 + w1 + w2 + w3 + w4;
    float sum_conv = (float)TT * bias + wsum * S
                   - w0 * (xv[TT - 2] + xv[TT - 1]) - w1 * xv[TT - 1]
                   - w3 * xv[0] - w4 * (xv[0] + xv[1]);

    const float mean  = sum_conv * (1.0f / (float)TT);
    const float watt  = 1.0f / (1.0f + expf(-satt * mean));
    const float scale = 1.0f + 0.5f * watt;          // GAMMA = 0.5
    const float bsc   = bias * scale;                // folded bias*scale

    // ---------- LIF recurrence, fully register-resident ----------
    const float HALF_PI = 1.5707964f;
    const float INV2PI  = 0.15915494f;
    const float K3      = 0.1f / 3.0f;
    const float thr0c   = 0.1f * thr0;

    float mem = 0.f;
    float thr = thr0;
    float h1 = 0.f, h2 = 0.f;

    #pragma unroll
    for (int t = 0; t < TT; ++t) {
        // conv window straight from the register array (compile-time indices)
        const float xm2 = (t >= 2)      ? xv[t - 2] : 0.f;
        const float xm1 = (t >= 1)      ? xv[t - 1] : 0.f;
        const float x0  = xv[t];
        const float xp1 = (t < TT - 1)  ? xv[t + 1] : 0.f;
        const float xp2 = (t < TT - 2)  ? xv[t + 2] : 0.f;

        float cv = fmaf(w1, xm1, w0 * xm2);
        cv = fmaf(w2, x0,  cv);
        cv = fmaf(w3, xp1, cv);
        cv = fmaf(w4, xp2, cv);
        const float xt = fmaf(cv, scale, bsc);

        mem = fmaf(0.9f, mem, xt);                   // DECAY

        // thr pre-term runs in parallel with the atan chain
        const float pre = fmaf(0.9f, thr, fmaf(K3, h1 + h2, thr0c));

        // spike = atan((mem-thr)*pi/2)/(2*pi) + 0.25, degree-9 minimax
        const float d  = mem - thr;
        const float a  = fabsf(d) * HALF_PI;
        const float rc = __fdividef(1.0f, a);        // MUFU.RCP
        const float tk = fminf(a, rc);
        const float t2 = tk * tk;
        const float t4 = t2 * t2;
        float e0 = fmaf(t2, -0.3302995f, 0.9998660f);
        float e1 = fmaf(t2, -0.0851330f, 0.1801410f);
        e1 = fmaf(t4, 0.0208351f, e1);
        float pr = fmaf(t4, e1, e0);
        float r  = tk * pr;
        r = (a > 1.0f) ? (HALF_PI - r) : r;
        r = copysignf(r, d);
        const float spike = fmaf(r, INV2PI, 0.25f);

        thr = fmaf(K3, spike, pre);
        mem = fmaf(-spike, thr, mem);
        h1 = h2; h2 = spike;

        __stcs(&op[t * FF], spike);                  // streaming store
    }

    // mem output appended after spikes
    out[(size_t)BB * TT * FF + g] = mem;
}

extern "C" void kernel_launch(void* const* d_in, const int* in_sizes, int n_in,
                              void* d_out, int out_size)
{
    const float* x    = (const float*)d_in[0];
    const float* thr0 = (const float*)d_in[1];
    const float* cw   = (const float*)d_in[2];
    const float* cb   = (const float*)d_in[3];
    const float* sa   = (const float*)d_in[4];
    float* out = (float*)d_out;

    const int lanes = BB * FF;                 // 262144 threads
    lif_fused_kernel<<<lanes / BLOCK, BLOCK>>>(x, thr0, cw, cb, sa, out);
}

// round 14
// speedup vs baseline: 1.1565x; 1.1565x over previous
#include <cuda_runtime.h>
#include <math_constants.h>

// EnhancedLIFNeuron: B=128, T=128, F=2048, KW=5 — two-kernel split.
// K1: reduction over t -> per-(b,f) attention scale (saturates HBM, warms L2).
// K2: fused conv + LIF recurrence (reads x mostly from L2, writes spikes).

#define TT     128
#define FF     2048
#define FH     (FF/2)      // ull (2 floats) stride per timestep = 1024
#define BB     128
#define BLK1   256
#define BLK2   128

typedef unsigned long long ull;

// 1 MB scratch for the per-lane packed scale (allowed: __device__ global)
__device__ ull g_scale[BB * FH];

// ---- packed f32x2 helpers ----
__device__ __forceinline__ ull pk2(float l, float h) {
    ull r; asm("mov.b64 %0, {%1, %2};" : "=l"(r) : "f"(l), "f"(h)); return r;
}
__device__ __forceinline__ void up2(float& l, float& h, ull v) {
    asm("mov.b64 {%0, %1}, %2;" : "=f"(l), "=f"(h) : "l"(v));
}
__device__ __forceinline__ ull fma2(ull a, ull b, ull c) {
    ull d; asm("fma.rn.f32x2 %0, %1, %2, %3;" : "=l"(d) : "l"(a), "l"(b), "l"(c)); return d;
}
__device__ __forceinline__ ull mul2(ull a, ull b) {
    ull d; asm("mul.rn.f32x2 %0, %1, %2;" : "=l"(d) : "l"(a), "l"(b)); return d;
}
__device__ __forceinline__ ull add2(ull a, ull b) {
    ull d; asm("add.rn.f32x2 %0, %1, %2;" : "=l"(d) : "l"(a), "l"(b)); return d;
}
__device__ __forceinline__ ull sub2(ull a, ull b) {
    ull d; asm("sub.rn.f32x2 %0, %1, %2;" : "=l"(d) : "l"(a), "l"(b)); return d;
}

// spike = atan((mem-thr)*pi/2)/(2*pi) + 0.25, packed 2 lanes.
__device__ __forceinline__ ull atan_spike(ull dd)
{
    const ull A1 = pk2( 0.9998660f,  0.9998660f);
    const ull A3 = pk2(-0.3302995f, -0.3302995f);
    const ull A5 = pk2( 0.1801410f,  0.1801410f);
    const ull A7 = pk2(-0.0851330f, -0.0851330f);
    const ull A9 = pk2( 0.0208351f,  0.0208351f);

    float dl, dh; up2(dl, dh, dd);
    float al = fabsf(dl) * 1.5707964f;
    float ah = fabsf(dh) * 1.5707964f;
    float rl = __fdividef(1.0f, al);
    float rh = __fdividef(1.0f, ah);
    ull tk  = pk2(fminf(al, rl), fminf(ah, rh));
    ull tt2 = mul2(tk, tk);
    ull tt4 = mul2(tt2, tt2);
    ull e0  = fma2(tt2, A3, A1);
    ull e1  = fma2(tt2, A7, A5);
    e1 = fma2(tt4, A9, e1);
    ull pp = fma2(tt4, e1, e0);
    ull rr = mul2(tk, pp);
    float prl, prh; up2(prl, prh, rr);
    float aal = (al > 1.0f) ? (1.5707964f - prl) : prl;
    float aah = (ah > 1.0f) ? (1.5707964f - prh) : prh;
    aal = copysignf(aal, dl);
    aah = copysignf(aah, dh);
    return pk2(fmaf(aal, 0.15915494f, 0.25f),
               fmaf(aah, 0.15915494f, 0.25f));
}

// ================= K1: reduction -> attention scale =================
// Reads x in REVERSE t order (default caching): when K1 ends, L2 holds x with
// the early-t lines freshest — exactly what K2 streams through first.
__global__ __launch_bounds__(BLK1)
void scale_kernel(const float* __restrict__ x,
                  const float* __restrict__ cw,
                  const float* __restrict__ cb,
                  const float* __restrict__ sa)
{
    const int p  = blockIdx.x * BLK1 + threadIdx.x;   // pair-lane id
    const int fp = p & (FH - 1);
    const int b  = p >> 10;

    const ull* __restrict__ xq = (const ull*)(x + (size_t)b * TT * FF + fp * 2);

    ull s0 = 0ull, s1 = 0ull, s2 = 0ull, s3 = 0ull;
    #pragma unroll 8
    for (int t = TT - 4; t >= 0; t -= 4) {
        s0 = add2(s0, xq[(t + 3) * FH]);
        s1 = add2(s1, xq[(t + 2) * FH]);
        s2 = add2(s2, xq[(t + 1) * FH]);
        s3 = add2(s3, xq[(t + 0) * FH]);
    }
    float Sx, Sy;
    up2(Sx, Sy, add2(add2(s0, s1), add2(s2, s3)));

    float e0l, e0h, e1l, e1h, t2l, t2h, t1l, t1h;
    up2(e0l, e0h, xq[0]);
    up2(e1l, e1h, xq[FH]);
    up2(t2l, t2h, xq[(TT - 2) * FH]);
    up2(t1l, t1h, xq[(TT - 1) * FH]);

    const float w0 = cw[0], w1 = cw[1], w3 = cw[3], w4 = cw[4];
    const float wsum = w0 + w1 + cw[2] + w3 + w4;
    const float cT = (float)TT * cb[0];
    const float satt = sa[0];

    float sc = cT + wsum * Sx - w0 * (t2l + t1l) - w1 * t1l
             - w3 * e0l - w4 * (e0l + e1l);
    float scx = 1.0f + 0.5f / (1.0f + expf(-satt * sc * (1.0f / (float)TT)));
    sc = cT + wsum * Sy - w0 * (t2h + t1h) - w1 * t1h
       - w3 * e0h - w4 * (e0h + e1h);
    float scy = 1.0f + 0.5f / (1.0f + expf(-satt * sc * (1.0f / (float)TT)));

    g_scale[p] = pk2(scx, scy);
}

// ================= K2: fused conv + LIF =================
__global__ __launch_bounds__(BLK2, 7)
void lif_kernel(const float* __restrict__ x,
                const float* __restrict__ thr_p,
                const float* __restrict__ cw,
                const float* __restrict__ cb,
                float* __restrict__ out)
{
    const int p  = blockIdx.x * BLK2 + threadIdx.x;   // pair-lane id
    const int fp = p & (FH - 1);
    const int b  = p >> 10;
    const int f  = fp * 2;

    const ull* __restrict__ xq = (const ull*)(x + (size_t)b * TT * FF + f);
    ull* __restrict__ oq       = (ull*)(out + (size_t)b * TT * FF + f);

    const float w0 = cw[0], w1 = cw[1], w2 = cw[2], w3 = cw[3], w4 = cw[4];
    const float bias = cb[0];
    const float thr0 = thr_p[0];

    const ull SCp = g_scale[p];
    float scx, scy; up2(scx, scy, SCp);
    const ull Bpp = pk2(bias * scx, bias * scy);

    const ull W0 = pk2(w0, w0), W1 = pk2(w1, w1), W2 = pk2(w2, w2);
    const ull W3 = pk2(w3, w3), W4 = pk2(w4, w4);
    const ull DEC = pk2(0.9f, 0.9f);
    const float k3f = 0.1f / 3.0f;
    const ull K3   = pk2(k3f, k3f);
    const ull TH0C = pk2(0.1f * thr0, 0.1f * thr0);

    // conv window + 8-deep register prefetch queue
    ull m2v = 0ull, m1v = 0ull;
    ull c0v = __ldcs(&xq[0]);
    ull p1v = __ldcs(&xq[FH]);

    ull Q[8];
    #pragma unroll
    for (int i = 0; i < 8; ++i) Q[i] = __ldcs(&xq[(2 + i) * FH]);

    ull memv = 0ull;
    ull thrv = pk2(thr0, thr0);
    ull h1v = 0ull, h2v = 0ull;

    // PFMODE: 1 = unconditional prefetch of x[T_+10]; 2 = guarded; 0 = none
    #define LIF_STEP(QI, T_, PFMODE)                                            \
    {                                                                            \
        ull p2v = Q[QI];                                                         \
        if ((PFMODE) == 1) {                                                     \
            Q[QI] = __ldcs(&xq[((T_) + 10) * FH]);                               \
        } else if ((PFMODE) == 2) {                                              \
            int idx_ = (T_) + 10;                                                \
            Q[QI] = (idx_ < TT) ? __ldcs(&xq[idx_ * FH]) : 0ull;                 \
        }                                                                        \
        ull cv = mul2(W0, m2v);                                                  \
        cv = fma2(W1, m1v, cv);                                                  \
        cv = fma2(W2, c0v, cv);                                                  \
        cv = fma2(W3, p1v, cv);                                                  \
        cv = fma2(W4, p2v, cv);                                                  \
        memv = fma2(DEC, memv, fma2(cv, SCp, Bpp));                              \
        ull pre = fma2(DEC, thrv, fma2(K3, add2(h1v, h2v), TH0C));               \
        ull sp = atan_spike(sub2(memv, thrv));                                   \
        thrv = fma2(K3, sp, pre);                                                \
        memv = sub2(memv, mul2(sp, thrv));                                       \
        h1v = h2v; h2v = sp;                                                     \
        __stcs(&oq[(T_) * FH], sp);                                              \
        m2v = m1v; m1v = c0v; c0v = p1v; p1v = p2v;                              \
    }

    // chunks 0..13: t = 0..111, prefetch t+10 <= 121 always valid
    #pragma unroll 1
    for (int c = 0; c < 14; ++c) {
        const int tb = c * 8;
        LIF_STEP(0, tb + 0, 1)
        LIF_STEP(1, tb + 1, 1)
        LIF_STEP(2, tb + 2, 1)
        LIF_STEP(3, tb + 3, 1)
        LIF_STEP(4, tb + 4, 1)
        LIF_STEP(5, tb + 5, 1)
        LIF_STEP(6, tb + 6, 1)
        LIF_STEP(7, tb + 7, 1)
    }
    // chunk 14: t = 112..119, prefetch idx 122..129 guarded (>=128 -> 0)
    LIF_STEP(0, 112, 2)
    LIF_STEP(1, 113, 2)
    LIF_STEP(2, 114, 2)
    LIF_STEP(3, 115, 2)
    LIF_STEP(4, 116, 2)
    LIF_STEP(5, 117, 2)
    LIF_STEP(6, 118, 2)
    LIF_STEP(7, 119, 2)
    // chunk 15: t = 120..127, no prefetch; Q holds x[122..127], 0, 0
    LIF_STEP(0, 120, 0)
    LIF_STEP(1, 121, 0)
    LIF_STEP(2, 122, 0)
    LIF_STEP(3, 123, 0)
    LIF_STEP(4, 124, 0)
    LIF_STEP(5, 125, 0)
    LIF_STEP(6, 126, 0)
    LIF_STEP(7, 127, 0)

    #undef LIF_STEP

    // mem output appended after spikes
    ((ull*)(out + (size_t)BB * TT * FF))[p] = memv;
}

extern "C" void kernel_launch(void* const* d_in, const int* in_sizes, int n_in,
                              void* d_out, int out_size)
{
    const float* x    = (const float*)d_in[0];
    const float* thr0 = (const float*)d_in[1];
    const float* cw   = (const float*)d_in[2];
    const float* cb   = (const float*)d_in[3];
    const float* sa   = (const float*)d_in[4];
    float* out = (float*)d_out;

    const int pairs = BB * FH;                       // 131072 lanes
    scale_kernel<<<pairs / BLK1, BLK1>>>(x, cw, cb, sa);
    lif_kernel<<<pairs / BLK2, BLK2>>>(x, thr0, cw, cb, out);
}